// round 13
// baseline (speedup 1.0000x reference)
#include <cuda_runtime.h>
#include <cuda_bf16.h>
#include <math.h>
#include <cstdint>

// Shapes: B=256, R=2048, M=65536, L=64, H=4, BH=1024
typedef unsigned long long ull;

// ---------------- device scratch ----------------
__device__ float g_pk[16 * 256 * 256];              // split-K partials [z][b][n] (4 MB)
__device__ __nv_bfloat16 g_key_hi[1024 * 64];       // scaled keys, bf16 hi  [bh][l]
__device__ __nv_bfloat16 g_key_lo[1024 * 64];       // scaled keys, bf16 lo
__device__ __nv_bfloat16 g_mem_hi[65536 * 64];      // memory, bf16 hi [m][l]
__device__ __nv_bfloat16 g_mem_lo[65536 * 64];      // memory, bf16 lo
__device__ float g_sumsP[1024 * 4096];              // per (row, mt*4+wc) partial expsums (16 MB)
__device__ float g_invsum[1024];

// ---------------- HMMA / ldmatrix / cp.async helpers ----------------
__device__ __forceinline__ void mma_bf16(float* d, uint32_t a0, uint32_t a1,
                                         uint32_t a2, uint32_t a3,
                                         uint32_t b0, uint32_t b1) {
    asm volatile(
        "mma.sync.aligned.m16n8k16.row.col.f32.bf16.bf16.f32 "
        "{%0,%1,%2,%3}, {%4,%5,%6,%7}, {%8,%9}, {%0,%1,%2,%3};"
        : "+f"(d[0]), "+f"(d[1]), "+f"(d[2]), "+f"(d[3])
        : "r"(a0), "r"(a1), "r"(a2), "r"(a3), "r"(b0), "r"(b1));
}
__device__ __forceinline__ void ldsm_x4(uint32_t& r0, uint32_t& r1, uint32_t& r2,
                                        uint32_t& r3, uint32_t addr) {
    asm volatile("ldmatrix.sync.aligned.m8n8.x4.shared.b16 {%0,%1,%2,%3}, [%4];"
                 : "=r"(r0), "=r"(r1), "=r"(r2), "=r"(r3) : "r"(addr));
}
__device__ __forceinline__ uint32_t smem_u32(const void* p) {
    uint32_t a;
    asm("{ .reg .u64 t; cvta.to.shared.u64 t, %1; cvt.u32.u64 %0, t; }" : "=r"(a) : "l"(p));
    return a;
}
#define CP16(dst, src) \
    asm volatile("cp.async.cg.shared.global [%0], [%1], 16;" :: "r"(dst), "l"(src))
#define CP_COMMIT() asm volatile("cp.async.commit_group;" ::: "memory")
#define CP_WAIT1()  asm volatile("cp.async.wait_group 1;" ::: "memory")
#define CP_WAIT0()  asm volatile("cp.async.wait_group 0;" ::: "memory")

// ---------------- front: memory -> bf16 hi/lo ----------------
__global__ void conv_mem(const float* __restrict__ mem) {
    size_t i = (size_t)blockIdx.x * 256 + threadIdx.x;
    const float4* p = (const float4*)mem + i * 2;
    float4 a = p[0], b = p[1];
    float v[8] = {a.x, a.y, a.z, a.w, b.x, b.y, b.z, b.w};
    __align__(16) __nv_bfloat16 hh[8], ll[8];
#pragma unroll
    for (int j = 0; j < 8; j++) {
        hh[j] = __float2bfloat16_rn(v[j]);
        ll[j] = __float2bfloat16_rn(v[j] - __bfloat162float(hh[j]));
    }
    *(uint4*)&g_mem_hi[i * 8] = *(uint4*)hh;
    *(uint4*)&g_mem_lo[i * 8] = *(uint4*)ll;
}

// ---------------- k1a_tc: tensor-core key projection, split-K 16 ----------------
static constexpr int K1_ROW = 80;                   // 32 bf16 = 64B data + 16B pad
static constexpr int K1_ARR = 128 * K1_ROW;         // 10240 per array

__global__ __launch_bounds__(256) void k1a_tc(const float* __restrict__ rs,
                                              const float* __restrict__ Wk) {
    __shared__ __align__(16) char sm[4 * K1_ARR];
    uint32_t sb = smem_u32(sm);
    int kid = blockIdx.x;
    int b0 = (kid & 1) * 128, n0 = ((kid >> 1) & 1) * 128;
    int z = kid >> 2, kb = z * 128;
    int tid = threadIdx.x, wid = tid >> 5, lid = tid & 31;
    int wr = wid >> 2, wc = wid & 3;
    int g = lid >> 2, c = lid & 3;

    float acc[4][4][4];
#pragma unroll
    for (int mi = 0; mi < 4; mi++)
#pragma unroll
        for (int ni = 0; ni < 4; ni++)
#pragma unroll
            for (int q = 0; q < 4; q++) acc[mi][ni][q] = 0.f;

    int rw = lid & 7;
    uint32_t aOff = (uint32_t)((wr * 64 + rw + ((lid >> 3) & 1) * 8) * K1_ROW
                               + ((lid >> 4) & 1) * 16);
    uint32_t bOff = (uint32_t)((wc * 32 + rw + ((lid >> 4) & 1) * 8) * K1_ROW
                               + ((lid >> 3) & 1) * 16);

    for (int ch = 0; ch < 4; ch++) {
        int k0 = kb + ch * 32;
        {
            int r = tid >> 1, half = tid & 1;
            const float* pa = rs + (size_t)(b0 + r) * 2048 + k0 + half * 16;
            const float* pb = Wk + (size_t)(n0 + r) * 2048 + k0 + half * 16;
            __align__(16) __nv_bfloat16 ah[16], al[16], bh[16], bl[16];
#pragma unroll
            for (int j = 0; j < 16; j++) {
                float va = pa[j], vb = pb[j];
                ah[j] = __float2bfloat16_rn(va);
                al[j] = __float2bfloat16_rn(va - __bfloat162float(ah[j]));
                bh[j] = __float2bfloat16_rn(vb);
                bl[j] = __float2bfloat16_rn(vb - __bfloat162float(bh[j]));
            }
            char* da = sm + r * K1_ROW + half * 32;
            *(uint4*)(da + 0 * K1_ARR)      = ((uint4*)ah)[0];
            *(uint4*)(da + 0 * K1_ARR + 16) = ((uint4*)ah)[1];
            *(uint4*)(da + 1 * K1_ARR)      = ((uint4*)al)[0];
            *(uint4*)(da + 1 * K1_ARR + 16) = ((uint4*)al)[1];
            *(uint4*)(da + 2 * K1_ARR)      = ((uint4*)bh)[0];
            *(uint4*)(da + 2 * K1_ARR + 16) = ((uint4*)bh)[1];
            *(uint4*)(da + 3 * K1_ARR)      = ((uint4*)bl)[0];
            *(uint4*)(da + 3 * K1_ARR + 16) = ((uint4*)bl)[1];
        }
        __syncthreads();

#pragma unroll
        for (int kk = 0; kk < 2; kk++) {
            uint32_t ah_[4][4], al_[4][4];
#pragma unroll
            for (int mi = 0; mi < 4; mi++) {
                uint32_t ao = sb + aOff + mi * 16 * K1_ROW + kk * 32;
                ldsm_x4(ah_[mi][0], ah_[mi][1], ah_[mi][2], ah_[mi][3], ao);
                ldsm_x4(al_[mi][0], al_[mi][1], al_[mi][2], al_[mi][3], ao + K1_ARR);
            }
#pragma unroll
            for (int p = 0; p < 2; p++) {
                uint32_t bh_[4], bl_[4];
                uint32_t bo = sb + 2 * K1_ARR + bOff + p * 16 * K1_ROW + kk * 32;
                ldsm_x4(bh_[0], bh_[1], bh_[2], bh_[3], bo);
                ldsm_x4(bl_[0], bl_[1], bl_[2], bl_[3], bo + K1_ARR);
#pragma unroll
                for (int mi = 0; mi < 4; mi++)
#pragma unroll
                    for (int q = 0; q < 2; q++) {
                        int ni = p * 2 + q;
                        mma_bf16(acc[mi][ni], ah_[mi][0], ah_[mi][1], ah_[mi][2], ah_[mi][3],
                                 bh_[q * 2], bh_[q * 2 + 1]);
                        mma_bf16(acc[mi][ni], ah_[mi][0], ah_[mi][1], ah_[mi][2], ah_[mi][3],
                                 bl_[q * 2], bl_[q * 2 + 1]);
                        mma_bf16(acc[mi][ni], al_[mi][0], al_[mi][1], al_[mi][2], al_[mi][3],
                                 bh_[q * 2], bh_[q * 2 + 1]);
                    }
            }
        }
        __syncthreads();
    }

#pragma unroll
    for (int mi = 0; mi < 4; mi++) {
        int br0 = b0 + wr * 64 + mi * 16 + g;
#pragma unroll
        for (int ni = 0; ni < 4; ni++) {
            int nc = n0 + wc * 32 + ni * 8 + 2 * c;
            *(float2*)&g_pk[(size_t)z * 65536 + br0 * 256 + nc] =
                make_float2(acc[mi][ni][0], acc[mi][ni][1]);
            *(float2*)&g_pk[(size_t)z * 65536 + (br0 + 8) * 256 + nc] =
                make_float2(acc[mi][ni][2], acc[mi][ni][3]);
        }
    }
}

// ---------------- k1b: finalize -> scaled bf16 hi/lo keys; one block per batch b ----------------
__global__ __launch_bounds__(256) void k1b_finalize(const float* __restrict__ rs,
                                                    const float* __restrict__ Wb,
                                                    const float* __restrict__ bk,
                                                    const float* __restrict__ bb) {
    int b = blockIdx.x;
    int n = threadIdx.x;              // 256 threads = 4 heads x 64 lanes
    int h = n >> 6, l = n & 63;

    float key = bk[n];
#pragma unroll
    for (int s = 0; s < 16; s++) key += g_pk[(size_t)s * 65536 + b * 256 + n];

    float bp = 0.f;
#pragma unroll 8
    for (int i = 0; i < 32; i++) {
        int idx = l + 64 * i;
        bp += rs[b * 2048 + idx] * Wb[h * 2048 + idx];
    }

    __shared__ float s1[256], s2[256];
    s1[n] = key * key; s2[n] = bp;
    __syncthreads();
    for (int o = 32; o > 0; o >>= 1) {
        if (l < o) { s1[n] += s1[n + o]; s2[n] += s2[n + o]; }
        __syncthreads();
    }
    float beta = s2[h * 64] + bb[h];
    beta = beta > 0.f ? beta : 0.f;
    float sk = key * (beta * rsqrtf(s1[h * 64]));
    __nv_bfloat16 hi = __float2bfloat16_rn(sk);
    __nv_bfloat16 lo = __float2bfloat16_rn(sk - __bfloat162float(hi));
    int bh = b * 4 + h;
    g_key_hi[bh * 64 + l] = hi;
    g_key_lo[bh * 64 + l] = lo;
}

// ---------------- k2: 3-CTA/SM persistent HMMA GEMM, tile 64bh x 64m ----------------
// Grid 16 bt x 28 mg = 448 CTAs (one wave at 3 CTAs/SM).
// 8 warps in 2x4 grid; warp tile 32bh x 16m; double-buffered B (64 rows).
static constexpr int ROW_B = 144;                       // smem row stride in bytes
static constexpr int ARR_B = 64 * ROW_B;                // 9216 per array (64 rows)
static constexpr int SM_A_HI = 0;
static constexpr int SM_A_LO = ARR_B;                   // 9216
static constexpr int SM_B0   = 2 * ARR_B;               // 18432
static constexpr int BUF_S   = 2 * ARR_B;               // hi at +0, lo at +ARR_B
static constexpr int SMEM_K2 = SM_B0 + 2 * BUF_S;       // 55296
static constexpr int MT_STRIDE = 28;
static constexpr int MT_TOT  = 1024;                    // m-tiles of 64

// B fill: 1024 chunks (2 arrays x 64 rows x 8) over 256 threads -> 4 CP16 each
__device__ __forceinline__ void fill_B(uint32_t sb, int buf, int m0, int tid) {
#pragma unroll
    for (int i = 0; i < 4; i++) {
        int it = tid + i * 256;
        int arr = it >> 9, rem = it & 511;
        int r = rem >> 3, c16 = rem & 7;
        const __nv_bfloat16* src =
            (arr ? g_mem_lo : g_mem_hi) + (size_t)(m0 + r) * 64 + c16 * 8;
        uint32_t dst = sb + SM_B0 + buf * BUF_S + arr * ARR_B + r * ROW_B + c16 * 16;
        CP16(dst, src);
    }
}

template <int PASS>
__global__ __launch_bounds__(256, 3) void k2_mma(float* __restrict__ out) {
    extern __shared__ char smem[];
    uint32_t sb = smem_u32(smem);
    int tid = threadIdx.x, wid = tid >> 5, lid = tid & 31;
    int wr = wid >> 2, wc = wid & 3;          // warp grid 2x4
    int g = lid >> 2, c = lid & 3;            // groupID / thread-in-group
    int bt = blockIdx.x, mg = blockIdx.y;
    int bh0 = bt * 64;

    // ---- prologue: A fill (1024 chunks) + B tile0
#pragma unroll
    for (int i = 0; i < 4; i++) {
        int it = tid + i * 256;
        int arr = it >> 9, rem = it & 511;
        int r = rem >> 3, c16 = rem & 7;
        const __nv_bfloat16* src =
            (arr ? g_key_lo : g_key_hi) + (size_t)(bh0 + r) * 64 + c16 * 8;
        uint32_t dst = sb + (arr ? SM_A_LO : SM_A_HI) + r * ROW_B + c16 * 16;
        CP16(dst, src);
    }
    fill_B(sb, 0, mg * 64, tid);
    CP_COMMIT();

    // ldmatrix lane address offsets
    int rw = lid & 7;
    uint32_t aOff = (uint32_t)((wr * 32 + rw + ((lid >> 3) & 1) * 8) * ROW_B
                               + ((lid >> 4) & 1) * 16);
    uint32_t bOff = (uint32_t)((wc * 16 + rw + ((lid >> 4) & 1) * 8) * ROW_B
                               + ((lid >> 3) & 1) * 16);

    float inv0[2], inv1[2];
    if (PASS == 1) {
#pragma unroll
        for (int mi = 0; mi < 2; mi++) {
            int r0 = bh0 + wr * 32 + mi * 16 + g;
            inv0[mi] = g_invsum[r0];
            inv1[mi] = g_invsum[r0 + 8];
        }
    }

    int mt = mg, buf = 0;
    while (true) {
        int next = mt + MT_STRIDE;
        if (next < MT_TOT) {
            fill_B(sb, buf ^ 1, next * 64, tid);
            CP_COMMIT();
            CP_WAIT1();
        } else {
            CP_WAIT0();
        }
        __syncthreads();                           // fills visible to all warps

        int m0 = mt * 64;
        uint32_t bBase = sb + SM_B0 + buf * BUF_S;

        float acc[2][2][4];
#pragma unroll
        for (int mi = 0; mi < 2; mi++)
#pragma unroll
            for (int ni = 0; ni < 2; ni++)
#pragma unroll
                for (int qq = 0; qq < 4; qq++) acc[mi][ni][qq] = 0.f;

#pragma unroll
        for (int kk = 0; kk < 4; kk++) {
            uint32_t ah[2][4], al[2][4];
#pragma unroll
            for (int mi = 0; mi < 2; mi++) {
                uint32_t ao = sb + aOff + mi * 16 * ROW_B + kk * 32;
                ldsm_x4(ah[mi][0], ah[mi][1], ah[mi][2], ah[mi][3], ao + SM_A_HI);
                ldsm_x4(al[mi][0], al[mi][1], al[mi][2], al[mi][3], ao + SM_A_LO);
            }
            uint32_t bh_[4], bl_[4];
            uint32_t bo = bBase + bOff + kk * 32;
            ldsm_x4(bh_[0], bh_[1], bh_[2], bh_[3], bo);
            ldsm_x4(bl_[0], bl_[1], bl_[2], bl_[3], bo + ARR_B);
#pragma unroll
            for (int mi = 0; mi < 2; mi++)
#pragma unroll
                for (int qq = 0; qq < 2; qq++) {
                    mma_bf16(acc[mi][qq], ah[mi][0], ah[mi][1], ah[mi][2], ah[mi][3],
                             bh_[qq * 2], bh_[qq * 2 + 1]);
                    mma_bf16(acc[mi][qq], ah[mi][0], ah[mi][1], ah[mi][2], ah[mi][3],
                             bl_[qq * 2], bl_[qq * 2 + 1]);
                    mma_bf16(acc[mi][qq], al[mi][0], al[mi][1], al[mi][2], al[mi][3],
                             bh_[qq * 2], bh_[qq * 2 + 1]);
                }
        }

        if (PASS == 0) {
            // per-warp-column partial expsums, direct STG
#pragma unroll
            for (int mi = 0; mi < 2; mi++) {
                float s0 = 0.f, s1 = 0.f;
#pragma unroll
                for (int ni = 0; ni < 2; ni++) {
                    s0 += __expf(acc[mi][ni][0]) + __expf(acc[mi][ni][1]);
                    s1 += __expf(acc[mi][ni][2]) + __expf(acc[mi][ni][3]);
                }
                s0 += __shfl_xor_sync(0xffffffffu, s0, 1);
                s0 += __shfl_xor_sync(0xffffffffu, s0, 2);
                s1 += __shfl_xor_sync(0xffffffffu, s1, 1);
                s1 += __shfl_xor_sync(0xffffffffu, s1, 2);
                if (c == 0) {
                    int r0 = bh0 + wr * 32 + mi * 16 + g;
                    g_sumsP[(size_t)r0 * 4096 + mt * 4 + wc] = s0;
                    g_sumsP[(size_t)(r0 + 8) * 4096 + mt * 4 + wc] = s1;
                }
            }
        } else {
#pragma unroll
            for (int mi = 0; mi < 2; mi++) {
                int r0 = bh0 + wr * 32 + mi * 16 + g;
                size_t ob0 = (size_t)r0 * 65536 + m0 + wc * 16;
                size_t ob1 = (size_t)(r0 + 8) * 65536 + m0 + wc * 16;
#pragma unroll
                for (int ni = 0; ni < 2; ni++) {
                    int col = ni * 8 + 2 * c;
                    float2 v0 = make_float2(__expf(acc[mi][ni][0]) * inv0[mi],
                                            __expf(acc[mi][ni][1]) * inv0[mi]);
                    float2 v1 = make_float2(__expf(acc[mi][ni][2]) * inv1[mi],
                                            __expf(acc[mi][ni][3]) * inv1[mi]);
                    *(float2*)&out[ob0 + col] = v0;
                    *(float2*)&out[ob1 + col] = v1;
                }
            }
        }

        __syncthreads();                           // buf reads done before next fill
        if (next >= MT_TOT) break;
        mt = next; buf ^= 1;
    }
}

// ---------------- k3: reduce partial sums -> 1/rowsum ----------------
__global__ __launch_bounds__(256) void k3_reduce() {
    int bh = blockIdx.x, t = threadIdx.x;   // 256 threads
    float s = 0.f;
#pragma unroll
    for (int j = 0; j < 16; j++) s += g_sumsP[(size_t)bh * 4096 + t + 256 * j];
    __shared__ float red[256];
    red[t] = s;
    __syncthreads();
    for (int o = 128; o > 0; o >>= 1) {
        if (t < o) red[t] += red[t + o];
        __syncthreads();
    }
    if (t == 0) g_invsum[bh] = 1.0f / red[0];
}

// ---------------- launch ----------------
extern "C" void kernel_launch(void* const* d_in, const int* in_sizes, int n_in,
                              void* d_out, int out_size) {
    const float* rs  = (const float*)d_in[0];   // [256, 2048]
    const float* mem = (const float*)d_in[1];   // [1, 65536, 64]
    const float* Wk  = (const float*)d_in[2];   // [256, 2048]
    const float* bk  = (const float*)d_in[3];   // [256]
    const float* Wb  = (const float*)d_in[4];   // [4, 2048]
    const float* bb  = (const float*)d_in[5];   // [4]
    float* out = (float*)d_out;                 // [256, 4, 65536]
    (void)in_sizes; (void)n_in; (void)out_size;

    cudaFuncSetAttribute(k2_mma<0>, cudaFuncAttributeMaxDynamicSharedMemorySize, SMEM_K2);
    cudaFuncSetAttribute(k2_mma<1>, cudaFuncAttributeMaxDynamicSharedMemorySize, SMEM_K2);

    conv_mem<<<2048, 256>>>(mem);
    k1a_tc<<<64, 256>>>(rs, Wk);
    k1b_finalize<<<256, 256>>>(rs, Wb, bk, bb);

    k2_mma<0><<<dim3(16, 28), 256, SMEM_K2>>>(nullptr);
    k3_reduce<<<1024, 256>>>();
    k2_mma<1><<<dim3(16, 28), 256, SMEM_K2>>>(out);
}

// round 14
// speedup vs baseline: 1.1144x; 1.1144x over previous
#include <cuda_runtime.h>
#include <cuda_bf16.h>
#include <math.h>
#include <cstdint>

// Shapes: B=256, R=2048, M=65536, L=64, H=4, BH=1024
typedef unsigned long long ull;

// ---------------- device scratch ----------------
__device__ float g_pk[16 * 256 * 256];              // split-K partials [z][b][n] (4 MB)
__device__ __nv_bfloat16 g_key_hi[1024 * 64];       // scaled keys, bf16 hi  [bh][l]
__device__ __nv_bfloat16 g_key_lo[1024 * 64];       // scaled keys, bf16 lo
__device__ __nv_bfloat16 g_mem_hi[65536 * 64];      // memory, bf16 hi [m][l]
__device__ __nv_bfloat16 g_mem_lo[65536 * 64];      // memory, bf16 lo
__device__ float g_sumsP[1024 * 2048];              // per (row, mt*4+wc) partial expsums (8 MB)
__device__ float g_invsum[1024];

// ---------------- HMMA / ldmatrix / cp.async helpers ----------------
__device__ __forceinline__ void mma_bf16(float* d, uint32_t a0, uint32_t a1,
                                         uint32_t a2, uint32_t a3,
                                         uint32_t b0, uint32_t b1) {
    asm volatile(
        "mma.sync.aligned.m16n8k16.row.col.f32.bf16.bf16.f32 "
        "{%0,%1,%2,%3}, {%4,%5,%6,%7}, {%8,%9}, {%0,%1,%2,%3};"
        : "+f"(d[0]), "+f"(d[1]), "+f"(d[2]), "+f"(d[3])
        : "r"(a0), "r"(a1), "r"(a2), "r"(a3), "r"(b0), "r"(b1));
}
__device__ __forceinline__ void ldsm_x4(uint32_t& r0, uint32_t& r1, uint32_t& r2,
                                        uint32_t& r3, uint32_t addr) {
    asm volatile("ldmatrix.sync.aligned.m8n8.x4.shared.b16 {%0,%1,%2,%3}, [%4];"
                 : "=r"(r0), "=r"(r1), "=r"(r2), "=r"(r3) : "r"(addr));
}
__device__ __forceinline__ uint32_t smem_u32(const void* p) {
    uint32_t a;
    asm("{ .reg .u64 t; cvta.to.shared.u64 t, %1; cvt.u32.u64 %0, t; }" : "=r"(a) : "l"(p));
    return a;
}
#define CP16(dst, src) \
    asm volatile("cp.async.cg.shared.global [%0], [%1], 16;" :: "r"(dst), "l"(src))
#define CP_COMMIT() asm volatile("cp.async.commit_group;" ::: "memory")
#define CP_WAIT1()  asm volatile("cp.async.wait_group 1;" ::: "memory")
#define CP_WAIT0()  asm volatile("cp.async.wait_group 0;" ::: "memory")
// per-pair named barrier: 2 warps (64 threads), barrier id 1+wc
#define PBAR(wcv) asm volatile("bar.sync %0, 64;" :: "r"(1 + (wcv)) : "memory")

// ---------------- k1a_tc + conv_mem merged launch ----------------
// blocks 0..2047: conv_mem (memory -> bf16 hi/lo)
// blocks 2048..2111: tensor-core key projection, split-K 16
static constexpr int K1_ROW = 80;                   // 32 bf16 = 64B data + 16B pad
static constexpr int K1_ARR = 128 * K1_ROW;         // 10240 per array

__global__ void k1a_tc(const float* __restrict__ mem,
                       const float* __restrict__ rs,
                       const float* __restrict__ Wk) {
    __shared__ __align__(16) char sm[4 * K1_ARR];
    int bid = blockIdx.x;
    if (bid < 2048) {
        // conv_mem: 8 floats per thread
        size_t i = (size_t)bid * 256 + threadIdx.x;
        const float4* p = (const float4*)mem + i * 2;
        float4 a = p[0], b = p[1];
        float v[8] = {a.x, a.y, a.z, a.w, b.x, b.y, b.z, b.w};
        __align__(16) __nv_bfloat16 hh[8], ll[8];
#pragma unroll
        for (int j = 0; j < 8; j++) {
            hh[j] = __float2bfloat16_rn(v[j]);
            ll[j] = __float2bfloat16_rn(v[j] - __bfloat162float(hh[j]));
        }
        *(uint4*)&g_mem_hi[i * 8] = *(uint4*)hh;
        *(uint4*)&g_mem_lo[i * 8] = *(uint4*)ll;
        return;
    }

    uint32_t sb = smem_u32(sm);
    int kid = bid - 2048;
    int b0 = (kid & 1) * 128, n0 = ((kid >> 1) & 1) * 128;
    int z = kid >> 2, kb = z * 128;
    int tid = threadIdx.x, wid = tid >> 5, lid = tid & 31;
    int wr = wid >> 2, wc = wid & 3;
    int g = lid >> 2, c = lid & 3;

    float acc[4][4][4];
#pragma unroll
    for (int mi = 0; mi < 4; mi++)
#pragma unroll
        for (int ni = 0; ni < 4; ni++)
#pragma unroll
            for (int q = 0; q < 4; q++) acc[mi][ni][q] = 0.f;

    int rw = lid & 7;
    uint32_t aOff = (uint32_t)((wr * 64 + rw + ((lid >> 3) & 1) * 8) * K1_ROW
                               + ((lid >> 4) & 1) * 16);
    uint32_t bOff = (uint32_t)((wc * 32 + rw + ((lid >> 4) & 1) * 8) * K1_ROW
                               + ((lid >> 3) & 1) * 16);

    for (int ch = 0; ch < 4; ch++) {
        int k0 = kb + ch * 32;
        {
            int r = tid >> 1, half = tid & 1;
            const float* pa = rs + (size_t)(b0 + r) * 2048 + k0 + half * 16;
            const float* pb = Wk + (size_t)(n0 + r) * 2048 + k0 + half * 16;
            __align__(16) __nv_bfloat16 ah[16], al[16], bh[16], bl[16];
#pragma unroll
            for (int j = 0; j < 16; j++) {
                float va = pa[j], vb = pb[j];
                ah[j] = __float2bfloat16_rn(va);
                al[j] = __float2bfloat16_rn(va - __bfloat162float(ah[j]));
                bh[j] = __float2bfloat16_rn(vb);
                bl[j] = __float2bfloat16_rn(vb - __bfloat162float(bh[j]));
            }
            char* da = sm + r * K1_ROW + half * 32;
            *(uint4*)(da + 0 * K1_ARR)      = ((uint4*)ah)[0];
            *(uint4*)(da + 0 * K1_ARR + 16) = ((uint4*)ah)[1];
            *(uint4*)(da + 1 * K1_ARR)      = ((uint4*)al)[0];
            *(uint4*)(da + 1 * K1_ARR + 16) = ((uint4*)al)[1];
            *(uint4*)(da + 2 * K1_ARR)      = ((uint4*)bh)[0];
            *(uint4*)(da + 2 * K1_ARR + 16) = ((uint4*)bh)[1];
            *(uint4*)(da + 3 * K1_ARR)      = ((uint4*)bl)[0];
            *(uint4*)(da + 3 * K1_ARR + 16) = ((uint4*)bl)[1];
        }
        __syncthreads();

#pragma unroll
        for (int kk = 0; kk < 2; kk++) {
            uint32_t ah_[4][4], al_[4][4];
#pragma unroll
            for (int mi = 0; mi < 4; mi++) {
                uint32_t ao = sb + aOff + mi * 16 * K1_ROW + kk * 32;
                ldsm_x4(ah_[mi][0], ah_[mi][1], ah_[mi][2], ah_[mi][3], ao);
                ldsm_x4(al_[mi][0], al_[mi][1], al_[mi][2], al_[mi][3], ao + K1_ARR);
            }
#pragma unroll
            for (int p = 0; p < 2; p++) {
                uint32_t bh_[4], bl_[4];
                uint32_t bo = sb + 2 * K1_ARR + bOff + p * 16 * K1_ROW + kk * 32;
                ldsm_x4(bh_[0], bh_[1], bh_[2], bh_[3], bo);
                ldsm_x4(bl_[0], bl_[1], bl_[2], bl_[3], bo + K1_ARR);
#pragma unroll
                for (int mi = 0; mi < 4; mi++)
#pragma unroll
                    for (int q = 0; q < 2; q++) {
                        int ni = p * 2 + q;
                        mma_bf16(acc[mi][ni], ah_[mi][0], ah_[mi][1], ah_[mi][2], ah_[mi][3],
                                 bh_[q * 2], bh_[q * 2 + 1]);
                        mma_bf16(acc[mi][ni], ah_[mi][0], ah_[mi][1], ah_[mi][2], ah_[mi][3],
                                 bl_[q * 2], bl_[q * 2 + 1]);
                        mma_bf16(acc[mi][ni], al_[mi][0], al_[mi][1], al_[mi][2], al_[mi][3],
                                 bh_[q * 2], bh_[q * 2 + 1]);
                    }
            }
        }
        __syncthreads();
    }

#pragma unroll
    for (int mi = 0; mi < 4; mi++) {
        int br0 = b0 + wr * 64 + mi * 16 + g;
#pragma unroll
        for (int ni = 0; ni < 4; ni++) {
            int nc = n0 + wc * 32 + ni * 8 + 2 * c;
            *(float2*)&g_pk[(size_t)z * 65536 + br0 * 256 + nc] =
                make_float2(acc[mi][ni][0], acc[mi][ni][1]);
            *(float2*)&g_pk[(size_t)z * 65536 + (br0 + 8) * 256 + nc] =
                make_float2(acc[mi][ni][2], acc[mi][ni][3]);
        }
    }
}

// ---------------- k1b: finalize -> scaled bf16 hi/lo keys; one block per batch b ----------------
__global__ __launch_bounds__(256) void k1b_finalize(const float* __restrict__ rs,
                                                    const float* __restrict__ Wb,
                                                    const float* __restrict__ bk,
                                                    const float* __restrict__ bb) {
    int b = blockIdx.x;
    int n = threadIdx.x;              // 256 threads = 4 heads x 64 lanes
    int h = n >> 6, l = n & 63;

    float key = bk[n];
#pragma unroll
    for (int s = 0; s < 16; s++) key += g_pk[(size_t)s * 65536 + b * 256 + n];

    float bp = 0.f;
#pragma unroll 8
    for (int i = 0; i < 32; i++) {
        int idx = l + 64 * i;
        bp += rs[b * 2048 + idx] * Wb[h * 2048 + idx];
    }

    __shared__ float s1[256], s2[256];
    s1[n] = key * key; s2[n] = bp;
    __syncthreads();
    for (int o = 32; o > 0; o >>= 1) {
        if (l < o) { s1[n] += s1[n + o]; s2[n] += s2[n + o]; }
        __syncthreads();
    }
    float beta = s2[h * 64] + bb[h];
    beta = beta > 0.f ? beta : 0.f;
    float sk = key * (beta * rsqrtf(s1[h * 64]));
    __nv_bfloat16 hi = __float2bfloat16_rn(sk);
    __nv_bfloat16 lo = __float2bfloat16_rn(sk - __bfloat162float(hi));
    int bh = b * 4 + h;
    g_key_hi[bh * 64 + l] = hi;
    g_key_lo[bh * 64 + l] = lo;
}

// ---------------- k2: persistent HMMA GEMM, per-pair pipelines (named barriers) --------
// Grid 8 bt x 37 mg = 296 CTAs (one wave at 2 CTAs/SM).
// 8 warps = 4 independent pairs; pair wc owns B rows [wc*32, wc*32+32) and
// double-buffers only its slice, synchronized by bar.sync(1+wc, 64).
static constexpr int ROW_B = 144;                       // smem row stride in bytes
static constexpr int ARR_B = 128 * ROW_B;               // 18432 per array
static constexpr int SM_A_HI = 0;
static constexpr int SM_A_LO = ARR_B;                   // 18432
static constexpr int SM_B0   = 2 * ARR_B;               // 36864 (buf stride 2*ARR_B)
static constexpr int BUF_S   = 2 * ARR_B;               // hi at +0, lo at +ARR_B
static constexpr int SMEM_K2 = SM_B0 + 2 * BUF_S;       // 110592
static constexpr int MT_STRIDE = 37;
static constexpr int MT_TOT  = 512;

// pair-local B slice fill: 512 chunks (2 arrays x 32 rows x 8) over 64 threads
__device__ __forceinline__ void fill_B_pair(uint32_t sb, int buf, int m0, int wc, int q) {
#pragma unroll
    for (int i = 0; i < 8; i++) {
        int it = q + i * 64;
        int arr = it >> 8, rem = it & 255;
        int rl = rem >> 3, c16 = rem & 7;
        int r = wc * 32 + rl;
        const __nv_bfloat16* src =
            (arr ? g_mem_lo : g_mem_hi) + (size_t)(m0 + r) * 64 + c16 * 8;
        uint32_t dst = sb + SM_B0 + buf * BUF_S + arr * ARR_B + r * ROW_B + c16 * 16;
        CP16(dst, src);
    }
}

template <int PASS>
__global__ __launch_bounds__(256, 2) void k2_mma(float* __restrict__ out) {
    extern __shared__ char smem[];
    uint32_t sb = smem_u32(smem);
    int tid = threadIdx.x, wid = tid >> 5, lid = tid & 31;
    int wr = wid >> 2, wc = wid & 3;          // warp grid 2x4
    int g = lid >> 2, c = lid & 3;            // groupID / thread-in-group
    int q = wr * 32 + lid;                    // pair-local thread index 0..63
    int bt = blockIdx.x, mg = blockIdx.y;
    int bh0 = bt * 128;

    // ---- prologue: A fill (all threads), drain, full sync
#pragma unroll
    for (int i = 0; i < 8; i++) {
        int it = tid + i * 256;
        int arr = it >> 10, rem = it & 1023;
        int r = rem >> 3, c16 = rem & 7;
        const __nv_bfloat16* src =
            (arr ? g_key_lo : g_key_hi) + (size_t)(bh0 + r) * 64 + c16 * 8;
        uint32_t dst = sb + (arr ? SM_A_LO : SM_A_HI) + r * ROW_B + c16 * 16;
        CP16(dst, src);
    }
    CP_COMMIT();
    CP_WAIT0();
    __syncthreads();

    // first B tile: pair-local fill
    fill_B_pair(sb, 0, mg * 128, wc, q);
    CP_COMMIT();

    // ldmatrix lane address offsets
    int rw = lid & 7;
    uint32_t aOff = (uint32_t)((wr * 64 + rw + ((lid >> 3) & 1) * 8) * ROW_B
                               + ((lid >> 4) & 1) * 16);
    uint32_t bOff = (uint32_t)((wc * 32 + rw + ((lid >> 4) & 1) * 8) * ROW_B
                               + ((lid >> 3) & 1) * 16);

    float inv0[4], inv1[4];
    if (PASS == 1) {
#pragma unroll
        for (int mi = 0; mi < 4; mi++) {
            int r0 = bh0 + wr * 64 + mi * 16 + g;
            inv0[mi] = g_invsum[r0];
            inv1[mi] = g_invsum[r0 + 8];
        }
    }

    int mt = mg, buf = 0;
    while (true) {
        int next = mt + MT_STRIDE;
        if (next < MT_TOT) {
            fill_B_pair(sb, buf ^ 1, next * 128, wc, q);   // safe: pair passed read-barrier
            CP_COMMIT();
            CP_WAIT1();                                    // fill(t) landed (own chunks)
        } else {
            CP_WAIT0();
        }
        PBAR(wc);                                          // partner's chunks visible

        int m0 = mt * 128;
        uint32_t bBase = sb + SM_B0 + buf * BUF_S;

        float acc[4][4][4];
#pragma unroll
        for (int mi = 0; mi < 4; mi++)
#pragma unroll
            for (int ni = 0; ni < 4; ni++)
#pragma unroll
                for (int qq = 0; qq < 4; qq++) acc[mi][ni][qq] = 0.f;

#pragma unroll
        for (int kk = 0; kk < 4; kk++) {
            uint32_t ah[4][4], al[4][4];
#pragma unroll
            for (int mi = 0; mi < 4; mi++) {
                uint32_t ao = sb + aOff + mi * 16 * ROW_B + kk * 32;
                ldsm_x4(ah[mi][0], ah[mi][1], ah[mi][2], ah[mi][3], ao + SM_A_HI);
                ldsm_x4(al[mi][0], al[mi][1], al[mi][2], al[mi][3], ao + SM_A_LO);
            }
#pragma unroll
            for (int p = 0; p < 2; p++) {
                uint32_t bh_[4], bl_[4];
                uint32_t bo = bBase + bOff + p * 16 * ROW_B + kk * 32;
                ldsm_x4(bh_[0], bh_[1], bh_[2], bh_[3], bo);
                ldsm_x4(bl_[0], bl_[1], bl_[2], bl_[3], bo + ARR_B);
#pragma unroll
                for (int mi = 0; mi < 4; mi++)
#pragma unroll
                    for (int qq = 0; qq < 2; qq++) {
                        int ni = p * 2 + qq;
                        mma_bf16(acc[mi][ni], ah[mi][0], ah[mi][1], ah[mi][2], ah[mi][3],
                                 bh_[qq * 2], bh_[qq * 2 + 1]);
                        mma_bf16(acc[mi][ni], ah[mi][0], ah[mi][1], ah[mi][2], ah[mi][3],
                                 bl_[qq * 2], bl_[qq * 2 + 1]);
                        mma_bf16(acc[mi][ni], al[mi][0], al[mi][1], al[mi][2], al[mi][3],
                                 bh_[qq * 2], bh_[qq * 2 + 1]);
                    }
            }
        }

        PBAR(wc);                                          // pair done reading buf

        if (PASS == 0) {
#pragma unroll
            for (int mi = 0; mi < 4; mi++) {
                float s0 = 0.f, s1 = 0.f;
#pragma unroll
                for (int ni = 0; ni < 4; ni++) {
                    s0 += __expf(acc[mi][ni][0]) + __expf(acc[mi][ni][1]);
                    s1 += __expf(acc[mi][ni][2]) + __expf(acc[mi][ni][3]);
                }
                s0 += __shfl_xor_sync(0xffffffffu, s0, 1);
                s0 += __shfl_xor_sync(0xffffffffu, s0, 2);
                s1 += __shfl_xor_sync(0xffffffffu, s1, 1);
                s1 += __shfl_xor_sync(0xffffffffu, s1, 2);
                if (c == 0) {
                    int r0 = bh0 + wr * 64 + mi * 16 + g;
                    g_sumsP[(size_t)r0 * 2048 + mt * 4 + wc] = s0;
                    g_sumsP[(size_t)(r0 + 8) * 2048 + mt * 4 + wc] = s1;
                }
            }
        } else {
#pragma unroll
            for (int mi = 0; mi < 4; mi++) {
                int r0 = bh0 + wr * 64 + mi * 16 + g;
                size_t ob0 = (size_t)r0 * 65536 + m0 + wc * 32;
                size_t ob1 = (size_t)(r0 + 8) * 65536 + m0 + wc * 32;
#pragma unroll
                for (int ni = 0; ni < 4; ni++) {
                    int col = ni * 8 + 2 * c;
                    float2 v0 = make_float2(__expf(acc[mi][ni][0]) * inv0[mi],
                                            __expf(acc[mi][ni][1]) * inv0[mi]);
                    float2 v1 = make_float2(__expf(acc[mi][ni][2]) * inv1[mi],
                                            __expf(acc[mi][ni][3]) * inv1[mi]);
                    *(float2*)&out[ob0 + col] = v0;
                    *(float2*)&out[ob1 + col] = v1;
                }
            }
        }

        if (next >= MT_TOT) break;
        mt = next; buf ^= 1;
    }
}

// ---------------- k3: reduce partial sums -> 1/rowsum ----------------
__global__ __launch_bounds__(256) void k3_reduce() {
    int bh = blockIdx.x, t = threadIdx.x;   // 256 threads
    float s = 0.f;
#pragma unroll
    for (int j = 0; j < 8; j++) s += g_sumsP[(size_t)bh * 2048 + t + 256 * j];
    __shared__ float red[256];
    red[t] = s;
    __syncthreads();
    for (int o = 128; o > 0; o >>= 1) {
        if (t < o) red[t] += red[t + o];
        __syncthreads();
    }
    if (t == 0) g_invsum[bh] = 1.0f / red[0];
}

// ---------------- launch ----------------
extern "C" void kernel_launch(void* const* d_in, const int* in_sizes, int n_in,
                              void* d_out, int out_size) {
    const float* rs  = (const float*)d_in[0];   // [256, 2048]
    const float* mem = (const float*)d_in[1];   // [1, 65536, 64]
    const float* Wk  = (const float*)d_in[2];   // [256, 2048]
    const float* bk  = (const float*)d_in[3];   // [256]
    const float* Wb  = (const float*)d_in[4];   // [4, 2048]
    const float* bb  = (const float*)d_in[5];   // [4]
    float* out = (float*)d_out;                 // [256, 4, 65536]
    (void)in_sizes; (void)n_in; (void)out_size;

    cudaFuncSetAttribute(k2_mma<0>, cudaFuncAttributeMaxDynamicSharedMemorySize, SMEM_K2);
    cudaFuncSetAttribute(k2_mma<1>, cudaFuncAttributeMaxDynamicSharedMemorySize, SMEM_K2);

    k1a_tc<<<2112, 256>>>(mem, rs, Wk);
    k1b_finalize<<<256, 256>>>(rs, Wb, bk, bb);

    k2_mma<0><<<dim3(8, 37), 256, SMEM_K2>>>(nullptr);
    k3_reduce<<<1024, 256>>>();
    k2_mma<1><<<dim3(8, 37), 256, SMEM_K2>>>(out);
}

// round 15
// speedup vs baseline: 1.2099x; 1.0857x over previous
#include <cuda_runtime.h>
#include <cuda_bf16.h>
#include <math.h>
#include <cstdint>

// Shapes: B=256, R=2048, M=65536, L=64, H=4, BH=1024
typedef unsigned long long ull;

// ---------------- device scratch ----------------
__device__ float g_pk[16 * 256 * 256];              // split-K partials [z][b][n] (4 MB)
__device__ __nv_bfloat16 g_key_hi[1024 * 64];       // scaled keys, bf16 hi  [bh][l]
__device__ __nv_bfloat16 g_key_lo[1024 * 64];       // scaled keys, bf16 lo
__device__ __nv_bfloat16 g_mem_hi[65536 * 64];      // memory, bf16 hi [m][l]
__device__ __nv_bfloat16 g_mem_lo[65536 * 64];      // memory, bf16 lo
__device__ float g_sumsP[1024 * 160];               // per (row, mg*4+wc) partial expsums
__device__ float g_invsum[1024];

// ---------------- HMMA / ldmatrix / cp.async helpers ----------------
__device__ __forceinline__ void mma_bf16(float* d, uint32_t a0, uint32_t a1,
                                         uint32_t a2, uint32_t a3,
                                         uint32_t b0, uint32_t b1) {
    asm volatile(
        "mma.sync.aligned.m16n8k16.row.col.f32.bf16.bf16.f32 "
        "{%0,%1,%2,%3}, {%4,%5,%6,%7}, {%8,%9}, {%0,%1,%2,%3};"
        : "+f"(d[0]), "+f"(d[1]), "+f"(d[2]), "+f"(d[3])
        : "r"(a0), "r"(a1), "r"(a2), "r"(a3), "r"(b0), "r"(b1));
}
__device__ __forceinline__ void ldsm_x4(uint32_t& r0, uint32_t& r1, uint32_t& r2,
                                        uint32_t& r3, uint32_t addr) {
    asm volatile("ldmatrix.sync.aligned.m8n8.x4.shared.b16 {%0,%1,%2,%3}, [%4];"
                 : "=r"(r0), "=r"(r1), "=r"(r2), "=r"(r3) : "r"(addr));
}
__device__ __forceinline__ uint32_t smem_u32(const void* p) {
    uint32_t a;
    asm("{ .reg .u64 t; cvta.to.shared.u64 t, %1; cvt.u32.u64 %0, t; }" : "=r"(a) : "l"(p));
    return a;
}
#define CP16(dst, src) \
    asm volatile("cp.async.cg.shared.global [%0], [%1], 16;" :: "r"(dst), "l"(src))
#define CP_COMMIT() asm volatile("cp.async.commit_group;" ::: "memory")
#define CP_WAIT1()  asm volatile("cp.async.wait_group 1;" ::: "memory")
#define CP_WAIT0()  asm volatile("cp.async.wait_group 0;" ::: "memory")
// per-pair named barrier: 2 warps (64 threads), barrier id 1+wc
#define PBAR(wcv) asm volatile("bar.sync %0, 64;" :: "r"(1 + (wcv)) : "memory")

// ---------------- front: memory -> bf16 hi/lo ----------------
__global__ void conv_mem(const float* __restrict__ mem) {
    size_t i = (size_t)blockIdx.x * 256 + threadIdx.x;
    const float4* p = (const float4*)mem + i * 2;
    float4 a = p[0], b = p[1];
    float v[8] = {a.x, a.y, a.z, a.w, b.x, b.y, b.z, b.w};
    __align__(16) __nv_bfloat16 hh[8], ll[8];
#pragma unroll
    for (int j = 0; j < 8; j++) {
        hh[j] = __float2bfloat16_rn(v[j]);
        ll[j] = __float2bfloat16_rn(v[j] - __bfloat162float(hh[j]));
    }
    *(uint4*)&g_mem_hi[i * 8] = *(uint4*)hh;
    *(uint4*)&g_mem_lo[i * 8] = *(uint4*)ll;
}

// ---------------- k1a_tc: tensor-core key projection, split-K 16 ----------------
static constexpr int K1_ROW = 80;                   // 32 bf16 = 64B data + 16B pad
static constexpr int K1_ARR = 128 * K1_ROW;         // 10240 per array

__global__ __launch_bounds__(256) void k1a_tc(const float* __restrict__ rs,
                                              const float* __restrict__ Wk) {
    __shared__ __align__(16) char sm[4 * K1_ARR];
    uint32_t sb = smem_u32(sm);
    int kid = blockIdx.x;
    int b0 = (kid & 1) * 128, n0 = ((kid >> 1) & 1) * 128;
    int z = kid >> 2, kb = z * 128;
    int tid = threadIdx.x, wid = tid >> 5, lid = tid & 31;
    int wr = wid >> 2, wc = wid & 3;
    int g = lid >> 2, c = lid & 3;

    float acc[4][4][4];
#pragma unroll
    for (int mi = 0; mi < 4; mi++)
#pragma unroll
        for (int ni = 0; ni < 4; ni++)
#pragma unroll
            for (int q = 0; q < 4; q++) acc[mi][ni][q] = 0.f;

    int rw = lid & 7;
    uint32_t aOff = (uint32_t)((wr * 64 + rw + ((lid >> 3) & 1) * 8) * K1_ROW
                               + ((lid >> 4) & 1) * 16);
    uint32_t bOff = (uint32_t)((wc * 32 + rw + ((lid >> 4) & 1) * 8) * K1_ROW
                               + ((lid >> 3) & 1) * 16);

    for (int ch = 0; ch < 4; ch++) {
        int k0 = kb + ch * 32;
        {
            int r = tid >> 1, half = tid & 1;
            const float* pa = rs + (size_t)(b0 + r) * 2048 + k0 + half * 16;
            const float* pb = Wk + (size_t)(n0 + r) * 2048 + k0 + half * 16;
            __align__(16) __nv_bfloat16 ah[16], al[16], bh[16], bl[16];
#pragma unroll
            for (int j = 0; j < 16; j++) {
                float va = pa[j], vb = pb[j];
                ah[j] = __float2bfloat16_rn(va);
                al[j] = __float2bfloat16_rn(va - __bfloat162float(ah[j]));
                bh[j] = __float2bfloat16_rn(vb);
                bl[j] = __float2bfloat16_rn(vb - __bfloat162float(bh[j]));
            }
            char* da = sm + r * K1_ROW + half * 32;
            *(uint4*)(da + 0 * K1_ARR)      = ((uint4*)ah)[0];
            *(uint4*)(da + 0 * K1_ARR + 16) = ((uint4*)ah)[1];
            *(uint4*)(da + 1 * K1_ARR)      = ((uint4*)al)[0];
            *(uint4*)(da + 1 * K1_ARR + 16) = ((uint4*)al)[1];
            *(uint4*)(da + 2 * K1_ARR)      = ((uint4*)bh)[0];
            *(uint4*)(da + 2 * K1_ARR + 16) = ((uint4*)bh)[1];
            *(uint4*)(da + 3 * K1_ARR)      = ((uint4*)bl)[0];
            *(uint4*)(da + 3 * K1_ARR + 16) = ((uint4*)bl)[1];
        }
        __syncthreads();

#pragma unroll
        for (int kk = 0; kk < 2; kk++) {
            uint32_t ah_[4][4], al_[4][4];
#pragma unroll
            for (int mi = 0; mi < 4; mi++) {
                uint32_t ao = sb + aOff + mi * 16 * K1_ROW + kk * 32;
                ldsm_x4(ah_[mi][0], ah_[mi][1], ah_[mi][2], ah_[mi][3], ao);
                ldsm_x4(al_[mi][0], al_[mi][1], al_[mi][2], al_[mi][3], ao + K1_ARR);
            }
#pragma unroll
            for (int p = 0; p < 2; p++) {
                uint32_t bh_[4], bl_[4];
                uint32_t bo = sb + 2 * K1_ARR + bOff + p * 16 * K1_ROW + kk * 32;
                ldsm_x4(bh_[0], bh_[1], bh_[2], bh_[3], bo);
                ldsm_x4(bl_[0], bl_[1], bl_[2], bl_[3], bo + K1_ARR);
#pragma unroll
                for (int mi = 0; mi < 4; mi++)
#pragma unroll
                    for (int q = 0; q < 2; q++) {
                        int ni = p * 2 + q;
                        mma_bf16(acc[mi][ni], ah_[mi][0], ah_[mi][1], ah_[mi][2], ah_[mi][3],
                                 bh_[q * 2], bh_[q * 2 + 1]);
                        mma_bf16(acc[mi][ni], ah_[mi][0], ah_[mi][1], ah_[mi][2], ah_[mi][3],
                                 bl_[q * 2], bl_[q * 2 + 1]);
                        mma_bf16(acc[mi][ni], al_[mi][0], al_[mi][1], al_[mi][2], al_[mi][3],
                                 bh_[q * 2], bh_[q * 2 + 1]);
                    }
            }
        }
        __syncthreads();
    }

#pragma unroll
    for (int mi = 0; mi < 4; mi++) {
        int br0 = b0 + wr * 64 + mi * 16 + g;
#pragma unroll
        for (int ni = 0; ni < 4; ni++) {
            int nc = n0 + wc * 32 + ni * 8 + 2 * c;
            *(float2*)&g_pk[(size_t)z * 65536 + br0 * 256 + nc] =
                make_float2(acc[mi][ni][0], acc[mi][ni][1]);
            *(float2*)&g_pk[(size_t)z * 65536 + (br0 + 8) * 256 + nc] =
                make_float2(acc[mi][ni][2], acc[mi][ni][3]);
        }
    }
}

// ---------------- k1b: finalize -> scaled bf16 hi/lo keys; one block per batch b ----------------
__global__ __launch_bounds__(256) void k1b_finalize(const float* __restrict__ rs,
                                                    const float* __restrict__ Wb,
                                                    const float* __restrict__ bk,
                                                    const float* __restrict__ bb) {
    int b = blockIdx.x;
    int n = threadIdx.x;              // 256 threads = 4 heads x 64 lanes
    int h = n >> 6, l = n & 63;

    float key = bk[n];
#pragma unroll
    for (int s = 0; s < 16; s++) key += g_pk[(size_t)s * 65536 + b * 256 + n];

    float bp = 0.f;
#pragma unroll 8
    for (int i = 0; i < 32; i++) {
        int idx = l + 64 * i;
        bp += rs[b * 2048 + idx] * Wb[h * 2048 + idx];
    }

    __shared__ float s1[256], s2[256];
    s1[n] = key * key; s2[n] = bp;
    __syncthreads();
    for (int o = 32; o > 0; o >>= 1) {
        if (l < o) { s1[n] += s1[n + o]; s2[n] += s2[n + o]; }
        __syncthreads();
    }
    float beta = s2[h * 64] + bb[h];
    beta = beta > 0.f ? beta : 0.f;
    float sk = key * (beta * rsqrtf(s1[h * 64]));
    __nv_bfloat16 hi = __float2bfloat16_rn(sk);
    __nv_bfloat16 lo = __float2bfloat16_rn(sk - __bfloat162float(hi));
    int bh = b * 4 + h;
    g_key_hi[bh * 64 + l] = hi;
    g_key_lo[bh * 64 + l] = lo;
}

// ---------------- k2: persistent HMMA GEMM, per-pair pipelines (named barriers) --------
// Grid 8 bt x 37 mg = 296 CTAs (one wave at 2 CTAs/SM).
// 8 warps = 4 independent pairs; pair wc owns B rows [wc*32, wc*32+32) and
// double-buffers only its slice, synchronized by bar.sync(1+wc, 64).
// PASS 0: row-sum partials carried in registers across tiles, stored once.
static constexpr int ROW_B = 144;                       // smem row stride in bytes
static constexpr int ARR_B = 128 * ROW_B;               // 18432 per array
static constexpr int SM_A_HI = 0;
static constexpr int SM_A_LO = ARR_B;                   // 18432
static constexpr int SM_B0   = 2 * ARR_B;               // 36864 (buf stride 2*ARR_B)
static constexpr int BUF_S   = 2 * ARR_B;               // hi at +0, lo at +ARR_B
static constexpr int SMEM_K2 = SM_B0 + 2 * BUF_S;       // 110592
static constexpr int MT_STRIDE = 37;
static constexpr int MT_TOT  = 512;

// pair-local B slice fill: 512 chunks (2 arrays x 32 rows x 8) over 64 threads
__device__ __forceinline__ void fill_B_pair(uint32_t sb, int buf, int m0, int wc, int q) {
#pragma unroll
    for (int i = 0; i < 8; i++) {
        int it = q + i * 64;
        int arr = it >> 8, rem = it & 255;
        int rl = rem >> 3, c16 = rem & 7;
        int r = wc * 32 + rl;
        const __nv_bfloat16* src =
            (arr ? g_mem_lo : g_mem_hi) + (size_t)(m0 + r) * 64 + c16 * 8;
        uint32_t dst = sb + SM_B0 + buf * BUF_S + arr * ARR_B + r * ROW_B + c16 * 16;
        CP16(dst, src);
    }
}

template <int PASS>
__global__ __launch_bounds__(256, 2) void k2_mma(float* __restrict__ out) {
    extern __shared__ char smem[];
    uint32_t sb = smem_u32(smem);
    int tid = threadIdx.x, wid = tid >> 5, lid = tid & 31;
    int wr = wid >> 2, wc = wid & 3;          // warp grid 2x4
    int g = lid >> 2, c = lid & 3;            // groupID / thread-in-group
    int q = wr * 32 + lid;                    // pair-local thread index 0..63
    int bt = blockIdx.x, mg = blockIdx.y;
    int bh0 = bt * 128;

    // ---- prologue: A fill (all threads), drain, full sync
#pragma unroll
    for (int i = 0; i < 8; i++) {
        int it = tid + i * 256;
        int arr = it >> 10, rem = it & 1023;
        int r = rem >> 3, c16 = rem & 7;
        const __nv_bfloat16* src =
            (arr ? g_key_lo : g_key_hi) + (size_t)(bh0 + r) * 64 + c16 * 8;
        uint32_t dst = sb + (arr ? SM_A_LO : SM_A_HI) + r * ROW_B + c16 * 16;
        CP16(dst, src);
    }
    CP_COMMIT();
    CP_WAIT0();
    __syncthreads();

    // first B tile: pair-local fill
    fill_B_pair(sb, 0, mg * 128, wc, q);
    CP_COMMIT();

    // ldmatrix lane address offsets
    int rw = lid & 7;
    uint32_t aOff = (uint32_t)((wr * 64 + rw + ((lid >> 3) & 1) * 8) * ROW_B
                               + ((lid >> 4) & 1) * 16);
    uint32_t bOff = (uint32_t)((wc * 32 + rw + ((lid >> 4) & 1) * 8) * ROW_B
                               + ((lid >> 3) & 1) * 16);

    float inv0[4], inv1[4];
    if (PASS == 1) {
#pragma unroll
        for (int mi = 0; mi < 4; mi++) {
            int r0 = bh0 + wr * 64 + mi * 16 + g;
            inv0[mi] = g_invsum[r0];
            inv1[mi] = g_invsum[r0 + 8];
        }
    }

    // PASS 0: per-thread row-sum accumulators carried across tiles
    float rsum0[4], rsum1[4];
#pragma unroll
    for (int mi = 0; mi < 4; mi++) { rsum0[mi] = 0.f; rsum1[mi] = 0.f; }

    int mt = mg, buf = 0;
    while (true) {
        int next = mt + MT_STRIDE;
        if (next < MT_TOT) {
            fill_B_pair(sb, buf ^ 1, next * 128, wc, q);   // safe: pair passed read-barrier
            CP_COMMIT();
            CP_WAIT1();                                    // fill(t) landed (own chunks)
        } else {
            CP_WAIT0();
        }
        PBAR(wc);                                          // partner's chunks visible

        int m0 = mt * 128;
        uint32_t bBase = sb + SM_B0 + buf * BUF_S;

        float acc[4][4][4];
#pragma unroll
        for (int mi = 0; mi < 4; mi++)
#pragma unroll
            for (int ni = 0; ni < 4; ni++)
#pragma unroll
                for (int qq = 0; qq < 4; qq++) acc[mi][ni][qq] = 0.f;

#pragma unroll
        for (int kk = 0; kk < 4; kk++) {
            uint32_t ah[4][4], al[4][4];
#pragma unroll
            for (int mi = 0; mi < 4; mi++) {
                uint32_t ao = sb + aOff + mi * 16 * ROW_B + kk * 32;
                ldsm_x4(ah[mi][0], ah[mi][1], ah[mi][2], ah[mi][3], ao + SM_A_HI);
                ldsm_x4(al[mi][0], al[mi][1], al[mi][2], al[mi][3], ao + SM_A_LO);
            }
#pragma unroll
            for (int p = 0; p < 2; p++) {
                uint32_t bh_[4], bl_[4];
                uint32_t bo = bBase + bOff + p * 16 * ROW_B + kk * 32;
                ldsm_x4(bh_[0], bh_[1], bh_[2], bh_[3], bo);
                ldsm_x4(bl_[0], bl_[1], bl_[2], bl_[3], bo + ARR_B);
#pragma unroll
                for (int mi = 0; mi < 4; mi++)
#pragma unroll
                    for (int qq = 0; qq < 2; qq++) {
                        int ni = p * 2 + qq;
                        mma_bf16(acc[mi][ni], ah[mi][0], ah[mi][1], ah[mi][2], ah[mi][3],
                                 bh_[qq * 2], bh_[qq * 2 + 1]);
                        mma_bf16(acc[mi][ni], ah[mi][0], ah[mi][1], ah[mi][2], ah[mi][3],
                                 bl_[qq * 2], bl_[qq * 2 + 1]);
                        mma_bf16(acc[mi][ni], al[mi][0], al[mi][1], al[mi][2], al[mi][3],
                                 bh_[qq * 2], bh_[qq * 2 + 1]);
                    }
            }
        }

        PBAR(wc);                                          // pair done reading buf

        if (PASS == 0) {
            // accumulate per-thread partial row sums in registers (no shfl/STG here)
#pragma unroll
            for (int mi = 0; mi < 4; mi++) {
                float s0 = 0.f, s1 = 0.f;
#pragma unroll
                for (int ni = 0; ni < 4; ni++) {
                    s0 += __expf(acc[mi][ni][0]) + __expf(acc[mi][ni][1]);
                    s1 += __expf(acc[mi][ni][2]) + __expf(acc[mi][ni][3]);
                }
                rsum0[mi] += s0;
                rsum1[mi] += s1;
            }
        } else {
#pragma unroll
            for (int mi = 0; mi < 4; mi++) {
                int r0 = bh0 + wr * 64 + mi * 16 + g;
                size_t ob0 = (size_t)r0 * 65536 + m0 + wc * 32;
                size_t ob1 = (size_t)(r0 + 8) * 65536 + m0 + wc * 32;
#pragma unroll
                for (int ni = 0; ni < 4; ni++) {
                    int col = ni * 8 + 2 * c;
                    float2 v0 = make_float2(__expf(acc[mi][ni][0]) * inv0[mi],
                                            __expf(acc[mi][ni][1]) * inv0[mi]);
                    float2 v1 = make_float2(__expf(acc[mi][ni][2]) * inv1[mi],
                                            __expf(acc[mi][ni][3]) * inv1[mi]);
                    *(float2*)&out[ob0 + col] = v0;
                    *(float2*)&out[ob1 + col] = v1;
                }
            }
        }

        if (next >= MT_TOT) break;
        mt = next; buf ^= 1;
    }

    if (PASS == 0) {
        // final shfl-reduce across the 4 lanes of each group, store once per row
#pragma unroll
        for (int mi = 0; mi < 4; mi++) {
            float s0 = rsum0[mi], s1 = rsum1[mi];
            s0 += __shfl_xor_sync(0xffffffffu, s0, 1);
            s0 += __shfl_xor_sync(0xffffffffu, s0, 2);
            s1 += __shfl_xor_sync(0xffffffffu, s1, 1);
            s1 += __shfl_xor_sync(0xffffffffu, s1, 2);
            if (c == 0) {
                int r0 = bh0 + wr * 64 + mi * 16 + g;
                g_sumsP[(size_t)r0 * 160 + mg * 4 + wc] = s0;
                g_sumsP[(size_t)(r0 + 8) * 160 + mg * 4 + wc] = s1;
            }
        }
    }
}

// ---------------- k3: reduce partial sums -> 1/rowsum ----------------
__global__ __launch_bounds__(256) void k3_reduce() {
    int bh = blockIdx.x, t = threadIdx.x;   // 256 threads, 148 partials per row
    float s = (t < 148) ? g_sumsP[(size_t)bh * 160 + t] : 0.f;
    __shared__ float red[256];
    red[t] = s;
    __syncthreads();
    for (int o = 128; o > 0; o >>= 1) {
        if (t < o) red[t] += red[t + o];
        __syncthreads();
    }
    if (t == 0) g_invsum[bh] = 1.0f / red[0];
}

// ---------------- launch ----------------
extern "C" void kernel_launch(void* const* d_in, const int* in_sizes, int n_in,
                              void* d_out, int out_size) {
    const float* rs  = (const float*)d_in[0];   // [256, 2048]
    const float* mem = (const float*)d_in[1];   // [1, 65536, 64]
    const float* Wk  = (const float*)d_in[2];   // [256, 2048]
    const float* bk  = (const float*)d_in[3];   // [256]
    const float* Wb  = (const float*)d_in[4];   // [4, 2048]
    const float* bb  = (const float*)d_in[5];   // [4]
    float* out = (float*)d_out;                 // [256, 4, 65536]
    (void)in_sizes; (void)n_in; (void)out_size;

    cudaFuncSetAttribute(k2_mma<0>, cudaFuncAttributeMaxDynamicSharedMemorySize, SMEM_K2);
    cudaFuncSetAttribute(k2_mma<1>, cudaFuncAttributeMaxDynamicSharedMemorySize, SMEM_K2);

    conv_mem<<<2048, 256>>>(mem);
    k1a_tc<<<64, 256>>>(rs, Wk);
    k1b_finalize<<<256, 256>>>(rs, Wb, bk, bb);

    k2_mma<0><<<dim3(8, 37), 256, SMEM_K2>>>(nullptr);
    k3_reduce<<<1024, 256>>>();
    k2_mma<1><<<dim3(8, 37), 256, SMEM_K2>>>(out);
}

// round 16
// speedup vs baseline: 1.2651x; 1.0456x over previous
#include <cuda_runtime.h>
#include <cuda_bf16.h>
#include <math.h>
#include <cstdint>

// Shapes: B=256, R=2048, M=65536, L=64, H=4, BH=1024
typedef unsigned long long ull;

// ---------------- device scratch ----------------
__device__ float g_pk[16 * 256 * 256];              // split-K partials [z][b][n] (4 MB)
__device__ __nv_bfloat16 g_key_hi[1024 * 64];       // scaled keys, bf16 hi  [bh][l]
__device__ __nv_bfloat16 g_key_lo[1024 * 64];       // scaled keys, bf16 lo
__device__ __nv_bfloat16 g_mem_hi[65536 * 64];      // memory, bf16 hi [m][l]
__device__ __nv_bfloat16 g_mem_lo[65536 * 64];      // memory, bf16 lo
__device__ float g_sumsP[1024 * 160];               // per (row, mg*4+wc) partial expsums
__device__ float g_invsum[1024];

// ---------------- HMMA / ldmatrix / cp.async helpers ----------------
__device__ __forceinline__ void mma_bf16(float* d, uint32_t a0, uint32_t a1,
                                         uint32_t a2, uint32_t a3,
                                         uint32_t b0, uint32_t b1) {
    asm volatile(
        "mma.sync.aligned.m16n8k16.row.col.f32.bf16.bf16.f32 "
        "{%0,%1,%2,%3}, {%4,%5,%6,%7}, {%8,%9}, {%0,%1,%2,%3};"
        : "+f"(d[0]), "+f"(d[1]), "+f"(d[2]), "+f"(d[3])
        : "r"(a0), "r"(a1), "r"(a2), "r"(a3), "r"(b0), "r"(b1));
}
__device__ __forceinline__ void ldsm_x4(uint32_t& r0, uint32_t& r1, uint32_t& r2,
                                        uint32_t& r3, uint32_t addr) {
    asm volatile("ldmatrix.sync.aligned.m8n8.x4.shared.b16 {%0,%1,%2,%3}, [%4];"
                 : "=r"(r0), "=r"(r1), "=r"(r2), "=r"(r3) : "r"(addr));
}
__device__ __forceinline__ uint32_t smem_u32(const void* p) {
    uint32_t a;
    asm("{ .reg .u64 t; cvta.to.shared.u64 t, %1; cvt.u32.u64 %0, t; }" : "=r"(a) : "l"(p));
    return a;
}
#define CP16(dst, src) \
    asm volatile("cp.async.cg.shared.global [%0], [%1], 16;" :: "r"(dst), "l"(src))
#define CP_COMMIT() asm volatile("cp.async.commit_group;" ::: "memory")
#define CP_WAIT1()  asm volatile("cp.async.wait_group 1;" ::: "memory")
#define CP_WAIT0()  asm volatile("cp.async.wait_group 0;" ::: "memory")
// per-pair named barrier: 2 warps (64 threads), barrier id 1+wc
#define PBAR(wcv) asm volatile("bar.sync %0, 64;" :: "r"(1 + (wcv)) : "memory")

// ---------------- front: memory -> bf16 hi/lo ----------------
__global__ void conv_mem(const float* __restrict__ mem) {
    size_t i = (size_t)blockIdx.x * 256 + threadIdx.x;
    const float4* p = (const float4*)mem + i * 2;
    float4 a = p[0], b = p[1];
    float v[8] = {a.x, a.y, a.z, a.w, b.x, b.y, b.z, b.w};
    __align__(16) __nv_bfloat16 hh[8], ll[8];
#pragma unroll
    for (int j = 0; j < 8; j++) {
        hh[j] = __float2bfloat16_rn(v[j]);
        ll[j] = __float2bfloat16_rn(v[j] - __bfloat162float(hh[j]));
    }
    *(uint4*)&g_mem_hi[i * 8] = *(uint4*)hh;
    *(uint4*)&g_mem_lo[i * 8] = *(uint4*)ll;
}

// ---------------- k1a_tc: tensor-core key projection, split-K 16 ----------------
static constexpr int K1_ROW = 80;                   // 32 bf16 = 64B data + 16B pad
static constexpr int K1_ARR = 128 * K1_ROW;         // 10240 per array

__global__ __launch_bounds__(256) void k1a_tc(const float* __restrict__ rs,
                                              const float* __restrict__ Wk) {
    __shared__ __align__(16) char sm[4 * K1_ARR];
    uint32_t sb = smem_u32(sm);
    int kid = blockIdx.x;
    int b0 = (kid & 1) * 128, n0 = ((kid >> 1) & 1) * 128;
    int z = kid >> 2, kb = z * 128;
    int tid = threadIdx.x, wid = tid >> 5, lid = tid & 31;
    int wr = wid >> 2, wc = wid & 3;
    int g = lid >> 2, c = lid & 3;

    float acc[4][4][4];
#pragma unroll
    for (int mi = 0; mi < 4; mi++)
#pragma unroll
        for (int ni = 0; ni < 4; ni++)
#pragma unroll
            for (int q = 0; q < 4; q++) acc[mi][ni][q] = 0.f;

    int rw = lid & 7;
    uint32_t aOff = (uint32_t)((wr * 64 + rw + ((lid >> 3) & 1) * 8) * K1_ROW
                               + ((lid >> 4) & 1) * 16);
    uint32_t bOff = (uint32_t)((wc * 32 + rw + ((lid >> 4) & 1) * 8) * K1_ROW
                               + ((lid >> 3) & 1) * 16);

    for (int ch = 0; ch < 4; ch++) {
        int k0 = kb + ch * 32;
        {
            int r = tid >> 1, half = tid & 1;
            const float* pa = rs + (size_t)(b0 + r) * 2048 + k0 + half * 16;
            const float* pb = Wk + (size_t)(n0 + r) * 2048 + k0 + half * 16;
            __align__(16) __nv_bfloat16 ah[16], al[16], bh[16], bl[16];
#pragma unroll
            for (int j = 0; j < 16; j++) {
                float va = pa[j], vb = pb[j];
                ah[j] = __float2bfloat16_rn(va);
                al[j] = __float2bfloat16_rn(va - __bfloat162float(ah[j]));
                bh[j] = __float2bfloat16_rn(vb);
                bl[j] = __float2bfloat16_rn(vb - __bfloat162float(bh[j]));
            }
            char* da = sm + r * K1_ROW + half * 32;
            *(uint4*)(da + 0 * K1_ARR)      = ((uint4*)ah)[0];
            *(uint4*)(da + 0 * K1_ARR + 16) = ((uint4*)ah)[1];
            *(uint4*)(da + 1 * K1_ARR)      = ((uint4*)al)[0];
            *(uint4*)(da + 1 * K1_ARR + 16) = ((uint4*)al)[1];
            *(uint4*)(da + 2 * K1_ARR)      = ((uint4*)bh)[0];
            *(uint4*)(da + 2 * K1_ARR + 16) = ((uint4*)bh)[1];
            *(uint4*)(da + 3 * K1_ARR)      = ((uint4*)bl)[0];
            *(uint4*)(da + 3 * K1_ARR + 16) = ((uint4*)bl)[1];
        }
        __syncthreads();

#pragma unroll
        for (int kk = 0; kk < 2; kk++) {
            uint32_t ah_[4][4], al_[4][4];
#pragma unroll
            for (int mi = 0; mi < 4; mi++) {
                uint32_t ao = sb + aOff + mi * 16 * K1_ROW + kk * 32;
                ldsm_x4(ah_[mi][0], ah_[mi][1], ah_[mi][2], ah_[mi][3], ao);
                ldsm_x4(al_[mi][0], al_[mi][1], al_[mi][2], al_[mi][3], ao + K1_ARR);
            }
#pragma unroll
            for (int p = 0; p < 2; p++) {
                uint32_t bh_[4], bl_[4];
                uint32_t bo = sb + 2 * K1_ARR + bOff + p * 16 * K1_ROW + kk * 32;
                ldsm_x4(bh_[0], bh_[1], bh_[2], bh_[3], bo);
                ldsm_x4(bl_[0], bl_[1], bl_[2], bl_[3], bo + K1_ARR);
#pragma unroll
                for (int mi = 0; mi < 4; mi++)
#pragma unroll
                    for (int q = 0; q < 2; q++) {
                        int ni = p * 2 + q;
                        mma_bf16(acc[mi][ni], ah_[mi][0], ah_[mi][1], ah_[mi][2], ah_[mi][3],
                                 bh_[q * 2], bh_[q * 2 + 1]);
                        mma_bf16(acc[mi][ni], ah_[mi][0], ah_[mi][1], ah_[mi][2], ah_[mi][3],
                                 bl_[q * 2], bl_[q * 2 + 1]);
                        mma_bf16(acc[mi][ni], al_[mi][0], al_[mi][1], al_[mi][2], al_[mi][3],
                                 bh_[q * 2], bh_[q * 2 + 1]);
                    }
            }
        }
        __syncthreads();
    }

#pragma unroll
    for (int mi = 0; mi < 4; mi++) {
        int br0 = b0 + wr * 64 + mi * 16 + g;
#pragma unroll
        for (int ni = 0; ni < 4; ni++) {
            int nc = n0 + wc * 32 + ni * 8 + 2 * c;
            *(float2*)&g_pk[(size_t)z * 65536 + br0 * 256 + nc] =
                make_float2(acc[mi][ni][0], acc[mi][ni][1]);
            *(float2*)&g_pk[(size_t)z * 65536 + (br0 + 8) * 256 + nc] =
                make_float2(acc[mi][ni][2], acc[mi][ni][3]);
        }
    }
}

// ---------------- k1b: finalize -> scaled bf16 hi/lo keys; one block per batch b ----------------
__global__ __launch_bounds__(256) void k1b_finalize(const float* __restrict__ rs,
                                                    const float* __restrict__ Wb,
                                                    const float* __restrict__ bk,
                                                    const float* __restrict__ bb) {
    int b = blockIdx.x;
    int n = threadIdx.x;              // 256 threads = 4 heads x 64 lanes
    int h = n >> 6, l = n & 63;

    float key = bk[n];
#pragma unroll
    for (int s = 0; s < 16; s++) key += g_pk[(size_t)s * 65536 + b * 256 + n];

    float bp = 0.f;
#pragma unroll 8
    for (int i = 0; i < 32; i++) {
        int idx = l + 64 * i;
        bp += rs[b * 2048 + idx] * Wb[h * 2048 + idx];
    }

    __shared__ float s1[256], s2[256];
    s1[n] = key * key; s2[n] = bp;
    __syncthreads();
    for (int o = 32; o > 0; o >>= 1) {
        if (l < o) { s1[n] += s1[n + o]; s2[n] += s2[n + o]; }
        __syncthreads();
    }
    float beta = s2[h * 64] + bb[h];
    beta = beta > 0.f ? beta : 0.f;
    float sk = key * (beta * rsqrtf(s1[h * 64]));
    __nv_bfloat16 hi = __float2bfloat16_rn(sk);
    __nv_bfloat16 lo = __float2bfloat16_rn(sk - __bfloat162float(hi));
    int bh = b * 4 + h;
    g_key_hi[bh * 64 + l] = hi;
    g_key_lo[bh * 64 + l] = lo;
}

// ---------------- k2: persistent HMMA GEMM, per-pair pipelines (named barriers) --------
// Grid 8 bt x 37 mg = 296 CTAs (one wave at 2 CTAs/SM).
// PASS 0: row-sum partials carried in registers across tiles, stored once.
// PASS 1: output stores use __stcs (streaming) to avoid L2 write pollution.
static constexpr int ROW_B = 144;                       // smem row stride in bytes
static constexpr int ARR_B = 128 * ROW_B;               // 18432 per array
static constexpr int SM_A_HI = 0;
static constexpr int SM_A_LO = ARR_B;                   // 18432
static constexpr int SM_B0   = 2 * ARR_B;               // 36864 (buf stride 2*ARR_B)
static constexpr int BUF_S   = 2 * ARR_B;               // hi at +0, lo at +ARR_B
static constexpr int SMEM_K2 = SM_B0 + 2 * BUF_S;       // 110592
static constexpr int MT_STRIDE = 37;
static constexpr int MT_TOT  = 512;

// pair-local B slice fill: 512 chunks (2 arrays x 32 rows x 8) over 64 threads
__device__ __forceinline__ void fill_B_pair(uint32_t sb, int buf, int m0, int wc, int q) {
#pragma unroll
    for (int i = 0; i < 8; i++) {
        int it = q + i * 64;
        int arr = it >> 8, rem = it & 255;
        int rl = rem >> 3, c16 = rem & 7;
        int r = wc * 32 + rl;
        const __nv_bfloat16* src =
            (arr ? g_mem_lo : g_mem_hi) + (size_t)(m0 + r) * 64 + c16 * 8;
        uint32_t dst = sb + SM_B0 + buf * BUF_S + arr * ARR_B + r * ROW_B + c16 * 16;
        CP16(dst, src);
    }
}

template <int PASS>
__global__ __launch_bounds__(256, 2) void k2_mma(float* __restrict__ out) {
    extern __shared__ char smem[];
    uint32_t sb = smem_u32(smem);
    int tid = threadIdx.x, wid = tid >> 5, lid = tid & 31;
    int wr = wid >> 2, wc = wid & 3;          // warp grid 2x4
    int g = lid >> 2, c = lid & 3;            // groupID / thread-in-group
    int q = wr * 32 + lid;                    // pair-local thread index 0..63
    int bt = blockIdx.x, mg = blockIdx.y;
    int bh0 = bt * 128;

    // ---- prologue: A fill (all threads), drain, full sync
#pragma unroll
    for (int i = 0; i < 8; i++) {
        int it = tid + i * 256;
        int arr = it >> 10, rem = it & 1023;
        int r = rem >> 3, c16 = rem & 7;
        const __nv_bfloat16* src =
            (arr ? g_key_lo : g_key_hi) + (size_t)(bh0 + r) * 64 + c16 * 8;
        uint32_t dst = sb + (arr ? SM_A_LO : SM_A_HI) + r * ROW_B + c16 * 16;
        CP16(dst, src);
    }
    CP_COMMIT();
    CP_WAIT0();
    __syncthreads();

    // first B tile: pair-local fill
    fill_B_pair(sb, 0, mg * 128, wc, q);
    CP_COMMIT();

    // ldmatrix lane address offsets
    int rw = lid & 7;
    uint32_t aOff = (uint32_t)((wr * 64 + rw + ((lid >> 3) & 1) * 8) * ROW_B
                               + ((lid >> 4) & 1) * 16);
    uint32_t bOff = (uint32_t)((wc * 32 + rw + ((lid >> 4) & 1) * 8) * ROW_B
                               + ((lid >> 3) & 1) * 16);

    float inv0[4], inv1[4];
    if (PASS == 1) {
#pragma unroll
        for (int mi = 0; mi < 4; mi++) {
            int r0 = bh0 + wr * 64 + mi * 16 + g;
            inv0[mi] = g_invsum[r0];
            inv1[mi] = g_invsum[r0 + 8];
        }
    }

    // PASS 0: per-thread row-sum accumulators carried across tiles
    float rsum0[4], rsum1[4];
#pragma unroll
    for (int mi = 0; mi < 4; mi++) { rsum0[mi] = 0.f; rsum1[mi] = 0.f; }

    int mt = mg, buf = 0;
    while (true) {
        int next = mt + MT_STRIDE;
        if (next < MT_TOT) {
            fill_B_pair(sb, buf ^ 1, next * 128, wc, q);   // safe: pair passed read-barrier
            CP_COMMIT();
            CP_WAIT1();                                    // fill(t) landed (own chunks)
        } else {
            CP_WAIT0();
        }
        PBAR(wc);                                          // partner's chunks visible

        int m0 = mt * 128;
        uint32_t bBase = sb + SM_B0 + buf * BUF_S;

        float acc[4][4][4];
#pragma unroll
        for (int mi = 0; mi < 4; mi++)
#pragma unroll
            for (int ni = 0; ni < 4; ni++)
#pragma unroll
                for (int qq = 0; qq < 4; qq++) acc[mi][ni][qq] = 0.f;

#pragma unroll
        for (int kk = 0; kk < 4; kk++) {
            uint32_t ah[4][4], al[4][4];
#pragma unroll
            for (int mi = 0; mi < 4; mi++) {
                uint32_t ao = sb + aOff + mi * 16 * ROW_B + kk * 32;
                ldsm_x4(ah[mi][0], ah[mi][1], ah[mi][2], ah[mi][3], ao + SM_A_HI);
                ldsm_x4(al[mi][0], al[mi][1], al[mi][2], al[mi][3], ao + SM_A_LO);
            }
#pragma unroll
            for (int p = 0; p < 2; p++) {
                uint32_t bh_[4], bl_[4];
                uint32_t bo = bBase + bOff + p * 16 * ROW_B + kk * 32;
                ldsm_x4(bh_[0], bh_[1], bh_[2], bh_[3], bo);
                ldsm_x4(bl_[0], bl_[1], bl_[2], bl_[3], bo + ARR_B);
#pragma unroll
                for (int mi = 0; mi < 4; mi++)
#pragma unroll
                    for (int qq = 0; qq < 2; qq++) {
                        int ni = p * 2 + qq;
                        mma_bf16(acc[mi][ni], ah[mi][0], ah[mi][1], ah[mi][2], ah[mi][3],
                                 bh_[qq * 2], bh_[qq * 2 + 1]);
                        mma_bf16(acc[mi][ni], ah[mi][0], ah[mi][1], ah[mi][2], ah[mi][3],
                                 bl_[qq * 2], bl_[qq * 2 + 1]);
                        mma_bf16(acc[mi][ni], al[mi][0], al[mi][1], al[mi][2], al[mi][3],
                                 bh_[qq * 2], bh_[qq * 2 + 1]);
                    }
            }
        }

        PBAR(wc);                                          // pair done reading buf

        if (PASS == 0) {
            // accumulate per-thread partial row sums in registers (no shfl/STG here)
#pragma unroll
            for (int mi = 0; mi < 4; mi++) {
                float s0 = 0.f, s1 = 0.f;
#pragma unroll
                for (int ni = 0; ni < 4; ni++) {
                    s0 += __expf(acc[mi][ni][0]) + __expf(acc[mi][ni][1]);
                    s1 += __expf(acc[mi][ni][2]) + __expf(acc[mi][ni][3]);
                }
                rsum0[mi] += s0;
                rsum1[mi] += s1;
            }
        } else {
#pragma unroll
            for (int mi = 0; mi < 4; mi++) {
                int r0 = bh0 + wr * 64 + mi * 16 + g;
                size_t ob0 = (size_t)r0 * 65536 + m0 + wc * 32;
                size_t ob1 = (size_t)(r0 + 8) * 65536 + m0 + wc * 32;
#pragma unroll
                for (int ni = 0; ni < 4; ni++) {
                    int col = ni * 8 + 2 * c;
                    float2 v0 = make_float2(__expf(acc[mi][ni][0]) * inv0[mi],
                                            __expf(acc[mi][ni][1]) * inv0[mi]);
                    float2 v1 = make_float2(__expf(acc[mi][ni][2]) * inv1[mi],
                                            __expf(acc[mi][ni][3]) * inv1[mi]);
                    __stcs((float2*)&out[ob0 + col], v0);
                    __stcs((float2*)&out[ob1 + col], v1);
                }
            }
        }

        if (next >= MT_TOT) break;
        mt = next; buf ^= 1;
    }

    if (PASS == 0) {
        // final shfl-reduce across the 4 lanes of each group, store once per row
#pragma unroll
        for (int mi = 0; mi < 4; mi++) {
            float s0 = rsum0[mi], s1 = rsum1[mi];
            s0 += __shfl_xor_sync(0xffffffffu, s0, 1);
            s0 += __shfl_xor_sync(0xffffffffu, s0, 2);
            s1 += __shfl_xor_sync(0xffffffffu, s1, 1);
            s1 += __shfl_xor_sync(0xffffffffu, s1, 2);
            if (c == 0) {
                int r0 = bh0 + wr * 64 + mi * 16 + g;
                g_sumsP[(size_t)r0 * 160 + mg * 4 + wc] = s0;
                g_sumsP[(size_t)(r0 + 8) * 160 + mg * 4 + wc] = s1;
            }
        }
    }
}

// ---------------- k3: reduce partial sums -> 1/rowsum ----------------
__global__ __launch_bounds__(256) void k3_reduce() {
    int bh = blockIdx.x, t = threadIdx.x;   // 256 threads, 148 partials per row
    float s = (t < 148) ? g_sumsP[(size_t)bh * 160 + t] : 0.f;
    __shared__ float red[256];
    red[t] = s;
    __syncthreads();
    for (int o = 128; o > 0; o >>= 1) {
        if (t < o) red[t] += red[t + o];
        __syncthreads();
    }
    if (t == 0) g_invsum[bh] = 1.0f / red[0];
}

// ---------------- launch ----------------
extern "C" void kernel_launch(void* const* d_in, const int* in_sizes, int n_in,
                              void* d_out, int out_size) {
    const float* rs  = (const float*)d_in[0];   // [256, 2048]
    const float* mem = (const float*)d_in[1];   // [1, 65536, 64]
    const float* Wk  = (const float*)d_in[2];   // [256, 2048]
    const float* bk  = (const float*)d_in[3];   // [256]
    const float* Wb  = (const float*)d_in[4];   // [4, 2048]
    const float* bb  = (const float*)d_in[5];   // [4]
    float* out = (float*)d_out;                 // [256, 4, 65536]
    (void)in_sizes; (void)n_in; (void)out_size;

    cudaFuncSetAttribute(k2_mma<0>, cudaFuncAttributeMaxDynamicSharedMemorySize, SMEM_K2);
    cudaFuncSetAttribute(k2_mma<1>, cudaFuncAttributeMaxDynamicSharedMemorySize, SMEM_K2);

    conv_mem<<<2048, 256>>>(mem);
    k1a_tc<<<64, 256>>>(rs, Wk);
    k1b_finalize<<<256, 256>>>(rs, Wb, bk, bb);

    k2_mma<0><<<dim3(8, 37), 256, SMEM_K2>>>(nullptr);
    k3_reduce<<<1024, 256>>>();
    k2_mma<1><<<dim3(8, 37), 256, SMEM_K2>>>(out);
}